// round 1
// baseline (speedup 1.0000x reference)
#include <cuda_runtime.h>
#include <math.h>

#define NODES   50000
#define HID     128
#define GROUP   4
#define NGROUPS (NODES / GROUP)   // 12500 exactly

// Scratch (allocation-free rule: __device__ globals)
__device__ float g_gsq[NODES];   // g_phi(v_src, a_src)^2 per node
__device__ float g_msg[NODES];   // aggregated messages per node

// ---------------------------------------------------------------------------
// Zero the message accumulator (must happen every launch for determinism)
// ---------------------------------------------------------------------------
__global__ void zero_msg_kernel() {
    int i = blockIdx.x * blockDim.x + threadIdx.x;
    if (i < NODES) g_msg[i] = 0.0f;
}

// ---------------------------------------------------------------------------
// Fused 3-layer MLP over nodes.
//   IN_DIM=3, SQUARE=true : g-pass, input (v, a0, a1), writes g_gsq
//   IN_DIM=5, SQUARE=false: f-pass, input (v, a0, a1, msg, exc), writes out
// Block = 128 threads (one per hidden unit). All weights cached in SMEM.
// Each block grid-strides over groups of 4 nodes to amortize weight loads.
// ---------------------------------------------------------------------------
template <int IN_DIM, bool SQUARE>
__global__ void __launch_bounds__(HID, 3) mlp_kernel(
    const float* __restrict__ v,
    const float* __restrict__ a,
    const float* __restrict__ exc,        // only used when IN_DIM==5
    const float* __restrict__ w0, const float* __restrict__ b0,
    const float* __restrict__ w1, const float* __restrict__ b1,
    const float* __restrict__ w2, const float* __restrict__ b2,
    float* __restrict__ out)              // only used when !SQUARE
{
    extern __shared__ float sm[];
    float* w1s   = sm;                       // 128*128
    float* w0s   = w1s + HID * HID;          // up to 5*128
    float* b0s   = w0s + 5 * HID;            // 128
    float* b1s   = b0s + HID;                // 128
    float* w2s   = b1s + HID;                // 128
    float* h0s   = w2s + HID;                // GROUP*128, layout [k][j]
    float* parts = h0s + GROUP * HID;        // 4 warps * GROUP

    const int t    = threadIdx.x;
    const int warp = t >> 5;
    const int lane = t & 31;

    // --- stage weights into shared memory ---
    {
        const float4* s4 = (const float4*)w1;
        float4*       d4 = (float4*)w1s;
        #pragma unroll
        for (int i = t; i < HID * HID / 4; i += HID) d4[i] = s4[i];
        for (int i = t; i < IN_DIM * HID; i += HID)  w0s[i] = w0[i];
        b0s[t] = b0[t];
        b1s[t] = b1[t];
        w2s[t] = w2[t];
    }
    const float b2v = b2[0];
    __syncthreads();

    for (int grp = blockIdx.x; grp < NGROUPS; grp += gridDim.x) {
        const int n0 = grp * GROUP;

        // ---- layer 0: h0[t] = tanh(x . w0[:,t] + b0[t]) for 4 nodes ----
        float h0v[GROUP];
        #pragma unroll
        for (int j = 0; j < GROUP; j++) {
            const int n = n0 + j;
            float acc = b0s[t];
            acc += v[n]       * w0s[0 * HID + t];
            acc += a[2 * n]   * w0s[1 * HID + t];
            acc += a[2 * n + 1] * w0s[2 * HID + t];
            if (IN_DIM == 5) {
                acc += g_msg[n] * w0s[3 * HID + t];
                acc += exc[n]   * w0s[4 * HID + t];
            }
            h0v[j] = tanhf(acc);
        }
        *(float4*)&h0s[t * GROUP] =
            make_float4(h0v[0], h0v[1], h0v[2], h0v[3]);
        __syncthreads();

        // ---- layer 1: 128x128, 4 nodes in flight ----
        float acc0 = b1s[t], acc1 = b1s[t], acc2 = b1s[t], acc3 = b1s[t];
        #pragma unroll 8
        for (int k = 0; k < HID; k++) {
            const float4 h = *(const float4*)&h0s[k * GROUP]; // broadcast
            const float  w = w1s[k * HID + t];                // conflict-free
            acc0 += h.x * w;
            acc1 += h.y * w;
            acc2 += h.z * w;
            acc3 += h.w * w;
        }

        // ---- layer 2: scalar output = sum_t tanh(h1[t]) * w2[t] + b2 ----
        const float w2v = w2s[t];
        float p[GROUP];
        p[0] = tanhf(acc0) * w2v;
        p[1] = tanhf(acc1) * w2v;
        p[2] = tanhf(acc2) * w2v;
        p[3] = tanhf(acc3) * w2v;

        #pragma unroll
        for (int j = 0; j < GROUP; j++) {
            float s = p[j];
            #pragma unroll
            for (int off = 16; off > 0; off >>= 1)
                s += __shfl_down_sync(0xffffffffu, s, off);
            if (lane == 0) parts[warp * GROUP + j] = s;
        }
        __syncthreads();

        if (t < GROUP) {
            float s = parts[t] + parts[GROUP + t] + parts[2 * GROUP + t] +
                      parts[3 * GROUP + t] + b2v;
            if (SQUARE) {
                g_gsq[n0 + t] = s * s;
            } else {
                out[n0 + t] = s;
            }
        }
        __syncthreads();   // protect h0s/parts before next group
    }
}

// ---------------------------------------------------------------------------
// Edge pass: msg[dst] += W[e] * gsq[src]   (gather + scatter-add)
// ---------------------------------------------------------------------------
__global__ void edge_kernel(const int* __restrict__ src,
                            const int* __restrict__ dst,
                            const float* __restrict__ W,
                            int n_edges)
{
    int i = blockIdx.x * blockDim.x + threadIdx.x;
    if (i < n_edges) {
        const float m = W[i] * g_gsq[src[i]];
        atomicAdd(&g_msg[dst[i]], m);
    }
}

// ---------------------------------------------------------------------------
extern "C" void kernel_launch(void* const* d_in, const int* in_sizes, int n_in,
                              void* d_out, int out_size)
{
    const float* v    = (const float*)d_in[0];
    const float* exc  = (const float*)d_in[1];
    const int*   esrc = (const int*)  d_in[2];
    const int*   edst = (const int*)  d_in[3];
    const float* a    = (const float*)d_in[4];
    const float* W    = (const float*)d_in[5];
    const float* g0w  = (const float*)d_in[6];
    const float* g0b  = (const float*)d_in[7];
    const float* g1w  = (const float*)d_in[8];
    const float* g1b  = (const float*)d_in[9];
    const float* g2w  = (const float*)d_in[10];
    const float* g2b  = (const float*)d_in[11];
    const float* f0w  = (const float*)d_in[12];
    const float* f0b  = (const float*)d_in[13];
    const float* f1w  = (const float*)d_in[14];
    const float* f1b  = (const float*)d_in[15];
    const float* f2w  = (const float*)d_in[16];
    const float* f2b  = (const float*)d_in[17];
    float*       out  = (float*)d_out;

    const int n_edges = in_sizes[2];

    // shared mem: w1(64KB) + w0(2.5KB) + b0/b1/w2 (1.5KB) + h0(2KB) + parts
    const int smem_bytes =
        (HID * HID + 5 * HID + 3 * HID + GROUP * HID + 4 * GROUP) * 4;

    cudaFuncSetAttribute(mlp_kernel<3, true>,
                         cudaFuncAttributeMaxDynamicSharedMemorySize, smem_bytes);
    cudaFuncSetAttribute(mlp_kernel<5, false>,
                         cudaFuncAttributeMaxDynamicSharedMemorySize, smem_bytes);

    const int mlp_grid = 148 * 3;

    zero_msg_kernel<<<(NODES + 255) / 256, 256>>>();

    mlp_kernel<3, true><<<mlp_grid, HID, smem_bytes>>>(
        v, a, nullptr, g0w, g0b, g1w, g1b, g2w, g2b, nullptr);

    edge_kernel<<<(n_edges + 255) / 256, 256>>>(esrc, edst, W, n_edges);

    mlp_kernel<5, false><<<mlp_grid, HID, smem_bytes>>>(
        v, a, exc, f0w, f0b, f1w, f1b, f2w, f2b, out);
}

// round 2
// speedup vs baseline: 1.4676x; 1.4676x over previous
#include <cuda_runtime.h>
#include <math.h>
#include <stdint.h>

#define NODES   50000
#define HID     128
#define MTILE   64
#define NBLOCKS ((NODES + MTILE - 1) / MTILE)   // 782

#define H_STRIDE 132   // 4 mod 32 -> conflict-free A-frag loads
#define W_STRIDE 136   // 8 mod 32 -> conflict-free B-frag loads

// Scratch (allocation-free rule: __device__ globals)
__device__ float g_gsq[NODES];   // g_phi(v,a)^2 per node
__device__ float g_msg[NODES];   // aggregated messages per node

// ---------------------------------------------------------------------------
__global__ void zero_msg_kernel() {
    int i = blockIdx.x * blockDim.x + threadIdx.x;
    if (i < NODES) g_msg[i] = 0.0f;
}

// ---------------------------------------------------------------------------
// tf32 helpers: split fp32 into hi(tf32) + lo(tf32 of residual).
// tf32x3: A*B ~= Ahi*Bhi + Ahi*Blo + Alo*Bhi  (error ~2^-22)
// ---------------------------------------------------------------------------
__device__ __forceinline__ uint32_t f2tf(float x) {
    uint32_t r;
    asm("cvt.rna.tf32.f32 %0, %1;" : "=r"(r) : "f"(x));
    return r;
}
__device__ __forceinline__ void split_tf(float x, uint32_t& hi, uint32_t& lo) {
    hi = f2tf(x);
    lo = f2tf(x - __uint_as_float(hi));
}
__device__ __forceinline__ void mma8(float* c, const uint32_t* a, const uint32_t* b) {
    asm volatile(
        "mma.sync.aligned.m16n8k8.row.col.f32.tf32.tf32.f32 "
        "{%0,%1,%2,%3}, {%4,%5,%6,%7}, {%8,%9}, {%0,%1,%2,%3};"
        : "+f"(c[0]), "+f"(c[1]), "+f"(c[2]), "+f"(c[3])
        : "r"(a[0]), "r"(a[1]), "r"(a[2]), "r"(a[3]),
          "r"(b[0]), "r"(b[1]));
}

// ---------------------------------------------------------------------------
// Fused 3-layer MLP over a tile of 64 nodes.
//   layer0 (K=IN_DIM) scalar -> H0 smem (tanh)
//   layer1 128x128 via tf32x3 tensor-core MMA (tanh in epilogue)
//   layer2 128->1 reduction from C fragments
// 8 warps: warp w -> m-tile (w&3) [16 rows], n-half (w>>2) [64 cols]
// ---------------------------------------------------------------------------
template <int IN_DIM, bool SQUARE>
__global__ void __launch_bounds__(256, 2) mlp_mma_kernel(
    const float* __restrict__ v,
    const float* __restrict__ a,
    const float* __restrict__ exc,
    const float* __restrict__ w0, const float* __restrict__ b0,
    const float* __restrict__ w1, const float* __restrict__ b1,
    const float* __restrict__ w2, const float* __restrict__ b2,
    float* __restrict__ out)
{
    extern __shared__ float sm[];
    float* Hs  = sm;                           // MTILE * H_STRIDE
    float* W1s = Hs + MTILE * H_STRIDE;        // HID * W_STRIDE
    float* xs  = W1s + HID * W_STRIDE;         // MTILE * IN_DIM
    float* w0s = xs + MTILE * 5;               // IN_DIM * HID
    float* b0s = w0s + 5 * HID;
    float* b1s = b0s + HID;
    float* w2s = b1s + HID;
    float* red = w2s + HID;                    // MTILE * 2

    const int t    = threadIdx.x;
    const int base = blockIdx.x * MTILE;

    // ---- stage weights / inputs ----
    {
        const float4* s4 = (const float4*)w1;
        for (int i = t; i < HID * HID / 4; i += 256) {
            float4 x4 = s4[i];
            int k = (i * 4) >> 7, n = (i * 4) & 127;
            float* d = &W1s[k * W_STRIDE + n];
            d[0] = x4.x; d[1] = x4.y; d[2] = x4.z; d[3] = x4.w;
        }
    }
    for (int i = t; i < IN_DIM * HID; i += 256) w0s[i] = w0[i];
    if (t < HID) { b0s[t] = b0[t]; b1s[t] = b1[t]; w2s[t] = w2[t]; }
    if (t < MTILE) {
        int ng = base + t;
        bool ok = ng < NODES;
        xs[t * IN_DIM + 0] = ok ? v[ng]        : 0.0f;
        xs[t * IN_DIM + 1] = ok ? a[2 * ng]    : 0.0f;
        xs[t * IN_DIM + 2] = ok ? a[2 * ng + 1]: 0.0f;
        if (IN_DIM == 5) {
            xs[t * IN_DIM + 3] = ok ? g_msg[ng] : 0.0f;
            xs[t * IN_DIM + 4] = ok ? exc[ng]   : 0.0f;
        }
    }
    __syncthreads();

    // ---- layer 0: H0 = tanh(x @ w0 + b0) ----
    for (int i = t; i < MTILE * HID; i += 256) {
        int node = i >> 7, hid = i & 127;
        float acc = b0s[hid];
        #pragma unroll
        for (int d = 0; d < IN_DIM; d++)
            acc += xs[node * IN_DIM + d] * w0s[d * HID + hid];
        Hs[node * H_STRIDE + hid] = tanhf(acc);
    }
    __syncthreads();

    // ---- layer 1: 64x128x128 GEMM, tf32x3 ----
    const int w    = t >> 5, lane = t & 31;
    const int mt   = w & 3,  nh   = w >> 2;
    const int r0   = lane >> 2, q = lane & 3;

    float C[8][4];
    #pragma unroll
    for (int i = 0; i < 8; i++) {
        C[i][0] = 0.f; C[i][1] = 0.f; C[i][2] = 0.f; C[i][3] = 0.f;
    }

    const float* Arow0 = &Hs[(mt * 16 + r0) * H_STRIDE];
    const float* Arow1 = Arow0 + 8 * H_STRIDE;

    #pragma unroll 4
    for (int ks = 0; ks < 16; ks++) {
        const int k0 = ks * 8;
        uint32_t Ahi[4], Alo[4];
        split_tf(Arow0[k0 + q],     Ahi[0], Alo[0]);
        split_tf(Arow1[k0 + q],     Ahi[1], Alo[1]);
        split_tf(Arow0[k0 + q + 4], Ahi[2], Alo[2]);
        split_tf(Arow1[k0 + q + 4], Ahi[3], Alo[3]);
        #pragma unroll
        for (int nt = 0; nt < 8; nt++) {
            const int col = nh * 64 + nt * 8 + r0;
            uint32_t Bhi[2], Blo[2];
            split_tf(W1s[(k0 + q)     * W_STRIDE + col], Bhi[0], Blo[0]);
            split_tf(W1s[(k0 + q + 4) * W_STRIDE + col], Bhi[1], Blo[1]);
            mma8(C[nt], Alo, Bhi);
            mma8(C[nt], Ahi, Blo);
            mma8(C[nt], Ahi, Bhi);
        }
    }

    // ---- layer 2 epilogue: out = sum_c tanh(C+b1)[c] * w2[c] + b2 ----
    float p0 = 0.f, p1 = 0.f;
    #pragma unroll
    for (int nt = 0; nt < 8; nt++) {
        const int c0 = nh * 64 + nt * 8 + q * 2;
        const float bb0 = b1s[c0], bb1 = b1s[c0 + 1];
        const float ww0 = w2s[c0], ww1 = w2s[c0 + 1];
        p0 += tanhf(C[nt][0] + bb0) * ww0 + tanhf(C[nt][1] + bb1) * ww1;
        p1 += tanhf(C[nt][2] + bb0) * ww0 + tanhf(C[nt][3] + bb1) * ww1;
    }
    p0 += __shfl_xor_sync(0xffffffffu, p0, 1);
    p0 += __shfl_xor_sync(0xffffffffu, p0, 2);
    p1 += __shfl_xor_sync(0xffffffffu, p1, 1);
    p1 += __shfl_xor_sync(0xffffffffu, p1, 2);
    if (q == 0) {
        red[(mt * 16 + r0)     * 2 + nh] = p0;
        red[(mt * 16 + r0 + 8) * 2 + nh] = p1;
    }
    __syncthreads();

    if (t < MTILE) {
        int ng = base + t;
        if (ng < NODES) {
            float s = red[t * 2] + red[t * 2 + 1] + b2[0];
            if (SQUARE) g_gsq[ng] = s * s;
            else        out[ng]   = s;
        }
    }
}

// ---------------------------------------------------------------------------
// Edge pass: msg[dst] += W[e] * gsq[src]
// ---------------------------------------------------------------------------
__global__ void edge_kernel(const int* __restrict__ src,
                            const int* __restrict__ dst,
                            const float* __restrict__ W,
                            int n_edges)
{
    int i = blockIdx.x * blockDim.x + threadIdx.x;
    if (i < n_edges) {
        const float m = W[i] * g_gsq[src[i]];
        atomicAdd(&g_msg[dst[i]], m);
    }
}

// ---------------------------------------------------------------------------
extern "C" void kernel_launch(void* const* d_in, const int* in_sizes, int n_in,
                              void* d_out, int out_size)
{
    const float* v    = (const float*)d_in[0];
    const float* exc  = (const float*)d_in[1];
    const int*   esrc = (const int*)  d_in[2];
    const int*   edst = (const int*)  d_in[3];
    const float* a    = (const float*)d_in[4];
    const float* W    = (const float*)d_in[5];
    const float* g0w  = (const float*)d_in[6];
    const float* g0b  = (const float*)d_in[7];
    const float* g1w  = (const float*)d_in[8];
    const float* g1b  = (const float*)d_in[9];
    const float* g2w  = (const float*)d_in[10];
    const float* g2b  = (const float*)d_in[11];
    const float* f0w  = (const float*)d_in[12];
    const float* f0b  = (const float*)d_in[13];
    const float* f1w  = (const float*)d_in[14];
    const float* f1b  = (const float*)d_in[15];
    const float* f2w  = (const float*)d_in[16];
    const float* f2b  = (const float*)d_in[17];
    float*       out  = (float*)d_out;

    const int n_edges = in_sizes[2];

    const int smem_bytes =
        (MTILE * H_STRIDE + HID * W_STRIDE + MTILE * 5 + 5 * HID +
         3 * HID + MTILE * 2) * (int)sizeof(float);   // ~109 KB

    cudaFuncSetAttribute(mlp_mma_kernel<3, true>,
                         cudaFuncAttributeMaxDynamicSharedMemorySize, smem_bytes);
    cudaFuncSetAttribute(mlp_mma_kernel<5, false>,
                         cudaFuncAttributeMaxDynamicSharedMemorySize, smem_bytes);

    zero_msg_kernel<<<(NODES + 255) / 256, 256>>>();

    mlp_mma_kernel<3, true><<<NBLOCKS, 256, smem_bytes>>>(
        v, a, nullptr, g0w, g0b, g1w, g1b, g2w, g2b, nullptr);

    edge_kernel<<<(n_edges + 255) / 256, 256>>>(esrc, edst, W, n_edges);

    mlp_mma_kernel<5, false><<<NBLOCKS, 256, smem_bytes>>>(
        v, a, exc, f0w, f0b, f1w, f1b, f2w, f2b, out);
}